// round 11
// baseline (speedup 1.0000x reference)
#include <cuda_runtime.h>
#include <cstdint>

// Resample2d (FlowNet2 bilinear warp), B=4, C=64, H=384, W=512.
//
// R10: R9 structure with the smem row stride fixed to SST=96 (== 0 mod 32),
// making LDS banks depend on column only -> near-conflict-free gathers.
// (R3/R4/R7/R9 all used strides == 17..21 mod 32, which made bank =
// (20*tr + tc) mod 32 collide at degree ~6 for random per-lane rows.)
//   Block = 64x32 outputs, 512 threads, 4 px/thread, 8 channels per block.
//   Window = 44x80 input tile at origin-clamped (shifted) position; fill is
//   contiguous 16B cp.async, 2-stage pipeline. Out-of-window taps (P~1e-9)
//   take the exact global-memory fallback.

static constexpr int B = 4;
static constexpr int C = 64;
static constexpr int H = 384;
static constexpr int W = 512;
static constexpr int HW = H * W;

static constexpr int TX = 64;
static constexpr int TY = 32;
static constexpr int HUP = 6;                  // halo rows above (nominal)
static constexpr int HL  = 8;                  // halo cols left (nominal)
static constexpr int TROWS = TY + 12;          // 44
static constexpr int TCOLS = TX + 16;          // 80
static constexpr int SST   = 96;               // smem row stride (== 0 mod 32)
static constexpr int SELEM = TROWS * SST;      // 4224 floats / stage (16.5KB)
static constexpr int F4PROW = TCOLS / 4;       // 20
static constexpr int FILLU  = TROWS * F4PROW;  // 880 float4 units
static constexpr int NTHR = 512;
static constexpr int CPB  = 8;                 // channels per block

__device__ __forceinline__ int iclamp(int v, int lo, int hi) {
    return min(max(v, lo), hi);
}

__device__ __forceinline__ void cp_async16(uint32_t dst, const float* src) {
    asm volatile("cp.async.cg.shared.global [%0], [%1], 16;" :: "r"(dst), "l"(src));
}
__device__ __forceinline__ void cp_commit() {
    asm volatile("cp.async.commit_group;" ::: "memory");
}
template <int N>
__device__ __forceinline__ void cp_wait() {
    asm volatile("cp.async.wait_group %0;" :: "n"(N) : "memory");
}

__global__ __launch_bounds__(NTHR, 3) void resample2d_kernel(
    const float* __restrict__ in1,
    const float* __restrict__ flow,
    float* __restrict__ out)
{
    __shared__ float tile[2][SELEM];

    int tid = threadIdx.x;
    int xb = blockIdx.x * TX;
    int yb = blockIdx.y * TY;
    int bz = blockIdx.z >> 3;          // batch
    int c0 = (blockIdx.z & 7) * CPB;   // first channel of this block's group

    // Shifted (origin-clamped) window: fill stays contiguous & 16B aligned.
    int wxs = iclamp(xb - HL,  0, W - TCOLS);
    int wys = iclamp(yb - HUP, 0, H - TROWS);

    int x  = xb + (tid & 63);
    int ry = tid >> 6;                 // 0..7 (pixel p at row ry + 8p)

    // ---- fill precompute: 2 float4 units per thread ----
    int gsrc[2], soff[2];
    #pragma unroll
    for (int k = 0; k < 2; ++k) {
        int u = tid + k * NTHR;
        int r = u / F4PROW;
        int c4 = u - r * F4PROW;
        bool v = (u < FILLU);
        gsrc[k] = v ? ((wys + r) * W + wxs + c4 * 4) : 0;
        soff[k] = v ? (r * SST + c4 * 4) : -1;
    }
    uint32_t smbase = (uint32_t)__cvta_generic_to_shared(&tile[0][0]);

    // ---- per-pixel flow preamble (4 pixels per thread) ----
    float fa[4], fbw[4];
    unsigned pk0[4], pk1[4];
    int fbmask = 0;
    int opix0 = (yb + ry) * W + x;     // pixel p at opix0 + p*8*W

    const float* fptr = flow + (size_t)bz * 2 * HW;
    #pragma unroll
    for (int p = 0; p < 4; ++p) {
        int y   = yb + ry + 8 * p;
        int pix = y * W + x;
        float dx = fptr[pix];
        float dy = fptr[HW + pix];

        float xf = (float)x + dx;
        float yf = (float)y + dy;
        float x0f = floorf(xf);
        float y0f = floorf(yf);
        fa[p]  = xf - x0f;
        fbw[p] = yf - y0f;

        int x0i = (int)x0f;
        int y0i = (int)y0f;
        int x0 = iclamp(x0i,     0, W - 1);
        int x1 = iclamp(x0i + 1, 0, W - 1);
        int y0 = iclamp(y0i,     0, H - 1);
        int y1 = iclamp(y0i + 1, 0, H - 1);

        int tc0 = x0 - wxs;
        int tc1 = x1 - wxs;
        int tr0 = y0 - wys;
        int tr1 = y1 - wys;

        bool ok = (tc0 >= 0) & (tc1 < TCOLS) & (tr0 >= 0) & (tr1 < TROWS);
        if (ok) {
            pk0[p] = (unsigned)(tr0 * SST + tc0) | ((unsigned)(tr0 * SST + tc1) << 16);
            pk1[p] = (unsigned)(tr1 * SST + tc0) | ((unsigned)(tr1 * SST + tc1) << 16);
        } else {
            fbmask |= 1 << p;
            pk0[p] = (unsigned)(y0 * W + x0);
            pk1[p] = (unsigned)(x1 - x0) | ((unsigned)(y1 - y0) << 1);
        }
    }

    const float* bin  = in1 + (size_t)bz * C * HW + (size_t)c0 * HW;
    float*       bout = out + (size_t)bz * C * HW + (size_t)c0 * HW;

    // ---- prologue: fill channel 0 into stage 0 ----
    {
        #pragma unroll
        for (int k = 0; k < 2; ++k)
            if (soff[k] >= 0) cp_async16(smbase + soff[k] * 4, bin + gsrc[k]);
        cp_commit();
    }

    for (int c = 0; c < CPB; ++c) {
        if (c + 1 < CPB) {
            const float* nsrc = bin + (size_t)(c + 1) * HW;
            uint32_t db = smbase + (uint32_t)(((c + 1) & 1) * SELEM * 4);
            #pragma unroll
            for (int k = 0; k < 2; ++k)
                if (soff[k] >= 0) cp_async16(db + soff[k] * 4, nsrc + gsrc[k]);
            cp_commit();
            cp_wait<1>();      // fill for channel c has landed
        } else {
            cp_wait<0>();
        }
        __syncthreads();

        const float* tl  = tile[c & 1];
        const float* src = bin + (size_t)c * HW;
        float*       dst = bout + (size_t)c * HW;

        #pragma unroll
        for (int p = 0; p < 4; ++p) {
            float a  = fa[p];
            float bw = fbw[p];
            float w00 = (1.0f - a) * (1.0f - bw);
            float w10 = a * (1.0f - bw);
            float w01 = (1.0f - a) * bw;
            float w11 = a * bw;

            float res;
            if (!((fbmask >> p) & 1)) {
                int t00 = pk0[p] & 0xffff;
                int t10 = pk0[p] >> 16;
                int t01 = pk1[p] & 0xffff;
                int t11 = pk1[p] >> 16;
                res = w00 * tl[t00] + w10 * tl[t10]
                    + w01 * tl[t01] + w11 * tl[t11];
            } else {
                int g00 = (int)pk0[p];
                int dxi = pk1[p] & 1;
                int dyi = (pk1[p] >> 1) & 1;
                const float* gp = src + g00;
                res = w00 * __ldg(gp)
                    + w10 * __ldg(gp + dxi)
                    + w01 * __ldg(gp + dyi * W)
                    + w11 * __ldg(gp + dyi * W + dxi);
            }
            dst[opix0 + p * 8 * W] = res;
        }
        __syncthreads();       // all reads of stage c&1 done before its refill
    }
}

extern "C" void kernel_launch(void* const* d_in, const int* in_sizes, int n_in,
                              void* d_out, int out_size)
{
    const float* in1  = (const float*)d_in[0];
    const float* flow = (const float*)d_in[1];
    float*       out  = (float*)d_out;

    dim3 grid(W / TX, H / TY, B * (C / CPB));   // 8 x 12 x 32 = 3072 blocks
    resample2d_kernel<<<grid, NTHR>>>(in1, flow, out);
}

// round 12
// speedup vs baseline: 1.7414x; 1.7414x over previous
#include <cuda_runtime.h>

// Resample2d (FlowNet2 bilinear warp), fixed shape B=4, C=64, H=384, W=512.
//
// R11: direct gather (R1 geometry — 32 consecutive x per gather instruction,
// proven optimal), with:
//   - 2 y-split pixels per thread (y and y+192): two independent tap sets in
//     separate instructions -> 2x latency tolerance, same wavefronts/output.
//   - channel unroll 2: 8 front-batched LDG/thread keeps the per-SM L1tex
//     queue (depth ~248) under the overflow threshold that R1's unroll-4
//     front-batching exceeded (8 warps x 16 LDG x ~3 lines ~ 397 > 248).
//   - __launch_bounds__(256, 6) to hold ~40 regs / 48 warps per SM.

static constexpr int B = 4;
static constexpr int C = 64;
static constexpr int H = 384;
static constexpr int W = 512;
static constexpr int HW = H * W;
static constexpr int HHALF = H / 2;              // 192
static constexpr int NTH = B * HHALF * W;        // 393216 threads

__global__ __launch_bounds__(256, 6) void resample2d_kernel(
    const float* __restrict__ in1,
    const float* __restrict__ flow,
    float* __restrict__ out)
{
    int idx = blockIdx.x * blockDim.x + threadIdx.x;
    if (idx >= NTH) return;

    int x = idx & (W - 1);            // W = 512
    int t = idx >> 9;                 // b*HHALF + y
    int y = t % HHALF;
    int b = t / HHALF;

    const float* fptr = flow + (size_t)b * 2 * HW;

    int   offA[4], offB[4];
    float wA[4],  wB[4];
    int   pixA, pixB;

    #pragma unroll
    for (int p = 0; p < 2; ++p) {
        int yy  = y + p * HHALF;      // y or y+192
        int pix = yy * W + x;
        float dx = fptr[pix];
        float dy = fptr[HW + pix];

        float xf = (float)x + dx;
        float yf = (float)yy + dy;
        float x0f = floorf(xf);
        float y0f = floorf(yf);
        float a  = xf - x0f;
        float bw = yf - y0f;

        int x0i = (int)x0f;
        int y0i = (int)y0f;
        int x0 = min(max(x0i,     0), W - 1);
        int x1 = min(max(x0i + 1, 0), W - 1);
        int y0 = min(max(y0i,     0), H - 1);
        int y1 = min(max(y0i + 1, 0), H - 1);

        int*   off = p ? offB : offA;
        float* wgt = p ? wB   : wA;
        off[0] = y0 * W + x0;
        off[1] = y0 * W + x1;
        off[2] = y1 * W + x0;
        off[3] = y1 * W + x1;
        wgt[0] = (1.0f - a) * (1.0f - bw);
        wgt[1] = a * (1.0f - bw);
        wgt[2] = (1.0f - a) * bw;
        wgt[3] = a * bw;
        if (p) pixB = pix; else pixA = pix;
    }

    const float* src = in1 + (size_t)b * C * HW;
    float*       dst = out + (size_t)b * C * HW;

    #pragma unroll 2
    for (int c = 0; c < C; ++c) {
        float a0 = __ldg(src + offA[0]);
        float a1 = __ldg(src + offA[1]);
        float a2 = __ldg(src + offA[2]);
        float a3 = __ldg(src + offA[3]);
        float b0 = __ldg(src + offB[0]);
        float b1 = __ldg(src + offB[1]);
        float b2 = __ldg(src + offB[2]);
        float b3 = __ldg(src + offB[3]);

        dst[pixA] = wA[0] * a0 + wA[1] * a1 + wA[2] * a2 + wA[3] * a3;
        dst[pixB] = wB[0] * b0 + wB[1] * b1 + wB[2] * b2 + wB[3] * b3;

        src += HW;
        dst += HW;
    }
}

extern "C" void kernel_launch(void* const* d_in, const int* in_sizes, int n_in,
                              void* d_out, int out_size)
{
    const float* in1  = (const float*)d_in[0];
    const float* flow = (const float*)d_in[1];
    float*       out  = (float*)d_out;

    int threads = 256;
    int blocks = (NTH + threads - 1) / threads;   // 1536
    resample2d_kernel<<<blocks, threads>>>(in1, flow, out);
}

// round 13
// speedup vs baseline: 2.5425x; 1.4601x over previous
#include <cuda_runtime.h>

// Resample2d (FlowNet2 bilinear warp), fixed shape B=4, C=64, H=384, W=512.
//
// R12: R1's proven-optimal geometry (1 pixel/thread, warps = 32 consecutive x,
// 4 scalar tap gathers reused over 64 channels — the measured L1-wavefront
// floor across 11 variants), plus:
//   - __stcs streaming stores: write-once output evicts first, keeping the
//     gather footprint of input1 resident in L2 longer.
//   - max-L1 carveout (no smem used).

static constexpr int B = 4;
static constexpr int C = 64;
static constexpr int H = 384;
static constexpr int W = 512;
static constexpr int HW = H * W;
static constexpr int NPIX = B * H * W;

__global__ __launch_bounds__(256) void resample2d_kernel(
    const float* __restrict__ in1,
    const float* __restrict__ flow,
    float* __restrict__ out)
{
    int idx = blockIdx.x * blockDim.x + threadIdx.x;
    if (idx >= NPIX) return;

    int x = idx & (W - 1);          // W = 512 = 2^9
    int t = idx >> 9;               // b*H + y
    int y = t % H;
    int b = t / H;

    int pix = y * W + x;
    const float* fptr = flow + (size_t)b * 2 * HW;
    float dx = fptr[pix];
    float dy = fptr[HW + pix];

    float xf = (float)x + dx;
    float yf = (float)y + dy;
    float x0f = floorf(xf);
    float y0f = floorf(yf);
    float a  = xf - x0f;            // frac x
    float bw = yf - y0f;            // frac y

    int x0i = (int)x0f;
    int y0i = (int)y0f;
    int x0 = min(max(x0i,     0), W - 1);
    int x1 = min(max(x0i + 1, 0), W - 1);
    int y0 = min(max(y0i,     0), H - 1);
    int y1 = min(max(y0i + 1, 0), H - 1);

    float w00 = (1.0f - a) * (1.0f - bw);
    float w10 = a * (1.0f - bw);
    float w01 = (1.0f - a) * bw;
    float w11 = a * bw;

    int i00 = y0 * W + x0;
    int i10 = y0 * W + x1;
    int i01 = y1 * W + x0;
    int i11 = y1 * W + x1;

    const float* p = in1 + (size_t)b * C * HW;
    float*       o = out + (size_t)b * C * HW + pix;

    #pragma unroll 4
    for (int c = 0; c < C; ++c) {
        size_t off = (size_t)c * HW;
        float v00 = __ldg(p + off + i00);
        float v10 = __ldg(p + off + i10);
        float v01 = __ldg(p + off + i01);
        float v11 = __ldg(p + off + i11);
        __stcs(o + off, w00 * v00 + w10 * v10 + w01 * v01 + w11 * v11);
    }
}

extern "C" void kernel_launch(void* const* d_in, const int* in_sizes, int n_in,
                              void* d_out, int out_size)
{
    const float* in1  = (const float*)d_in[0];
    const float* flow = (const float*)d_in[1];
    float*       out  = (float*)d_out;

    static bool attr_set = false;
    if (!attr_set) {
        cudaFuncSetAttribute(resample2d_kernel,
                             cudaFuncAttributePreferredSharedMemoryCarveout,
                             cudaSharedmemCarveoutMaxL1);
        attr_set = true;
    }

    int threads = 256;
    int blocks = (NPIX + threads - 1) / threads;   // 3072
    resample2d_kernel<<<blocks, threads>>>(in1, flow, out);
}